// round 14
// baseline (speedup 1.0000x reference)
#include <cuda_runtime.h>

#define BDIM 4096   // batch rows
#define IDIM 4096   // in features
#define ODIM 4096   // out features
#define RPB  4      // rows per fused block (software pipeline depth)

// Scratch (allocation-free rule: __device__ global)
__device__ float g_wsb[ODIM];   // bias[o] * sum_i weight[o,i]

// ---------------------------------------------------------------------------
// Kernel 1: wsb[o] = bias[o] * sum_i weight[o,i]
// 4096 blocks x 128 threads, plain LDG.128. Pure-load blocks — measured at the
// 6.9 TB/s chip ceiling while also draining the previous replay's L2-resident
// output writes. Unchanged.
// ---------------------------------------------------------------------------
__global__ __launch_bounds__(128) void wsum_kernel(
    const float* __restrict__ weight,
    const float* __restrict__ bias)
{
    const int row = blockIdx.x;
    const int tid = threadIdx.x;
    const float4* src = reinterpret_cast<const float4*>(
        weight + (size_t)row * IDIM);

    float s = 0.0f;
#pragma unroll
    for (int i = 0; i < 8; i++) {
        float4 v = src[tid + i * 128];
        s += (v.x + v.y) + (v.z + v.w);
    }

#pragma unroll
    for (int off = 16; off > 0; off >>= 1)
        s += __shfl_down_sync(0xFFFFFFFFu, s, off);

    __shared__ float warp_sums[4];
    if ((tid & 31) == 0) warp_sums[tid >> 5] = s;
    __syncthreads();

    if (tid == 0) {
        float total = (warp_sums[0] + warp_sums[1]) +
                      (warp_sums[2] + warp_sums[3]);
        g_wsb[row] = total * __ldg(&bias[row]);
    }
}

// ---------------------------------------------------------------------------
// Kernel 2 (pipelined fused): each block owns RPB=4 consecutive rows.
// Pipeline: row r+1's DRAM loads are issued BEFORE row r is reduced/stored,
// so the (L1/L2-bound) reduce+store phase of row r overlaps row r+1's DRAM
// read latency — every resident block keeps a load stream in flight for its
// whole lifetime instead of only ~half (the R5/R13 failure mode: 2.9 TB/s
// read rate because store phases generated zero DRAM demand).
// 256 threads; each thread covers 4 float4 columns per row (16+16 regs for
// the two row buffers). Stores are plain STG.128 -> absorb into L2, drain
// during the next replay's wsum read window.
// ---------------------------------------------------------------------------
__global__ __launch_bounds__(256) void fused_kernel(
    const float* __restrict__ input,
    const float* __restrict__ bias,
    float* __restrict__ out)
{
    const int tid  = threadIdx.x;
    const int row0 = blockIdx.x * RPB;

    const float4* bi4 = reinterpret_cast<const float4*>(bias);
    const float4* ws4 = reinterpret_cast<const float4*>(g_wsb);

    __shared__ float warp_sums[8];
    __shared__ float xs_sh;

    // Prologue: issue row0 loads.
    float4 cur[4], nxt[4];
    {
        const float4* s0 = reinterpret_cast<const float4*>(
            input + (size_t)row0 * IDIM);
#pragma unroll
        for (int i = 0; i < 4; i++) cur[i] = s0[tid + i * 256];
    }

#pragma unroll
    for (int r = 0; r < RPB; r++) {
        // Issue NEXT row's DRAM loads before consuming cur (overlap).
        if (r + 1 < RPB) {
            const float4* sn = reinterpret_cast<const float4*>(
                input + (size_t)(row0 + r + 1) * IDIM);
#pragma unroll
            for (int i = 0; i < 4; i++) nxt[i] = sn[tid + i * 256];
        }

        // Reduce cur -> xs (waits only on cur's scoreboard, not nxt's).
        float s = 0.0f;
#pragma unroll
        for (int i = 0; i < 4; i++)
            s += (cur[i].x + cur[i].y) + (cur[i].z + cur[i].w);

#pragma unroll
        for (int off = 16; off > 0; off >>= 1)
            s += __shfl_down_sync(0xFFFFFFFFu, s, off);

        if ((tid & 31) == 0) warp_sums[tid >> 5] = s;
        __syncthreads();
        if (tid == 0) {
            float t = ((warp_sums[0] + warp_sums[1]) +
                       (warp_sums[2] + warp_sums[3])) +
                      ((warp_sums[4] + warp_sums[5]) +
                       (warp_sums[6] + warp_sums[7]));
            xs_sh = t;
        }
        __syncthreads();
        const float xs = xs_sh;

        // Store row r (L1-hit bias/wsb loads + STG.128 to L2) — overlaps
        // the in-flight DRAM loads of row r+1.
        float4* dst = reinterpret_cast<float4*>(
            out + (size_t)(row0 + r) * ODIM);
#pragma unroll
        for (int i = 0; i < 4; i++) {
            const int c = tid + i * 256;
            float4 b = bi4[c];
            float4 w = ws4[c];
            float4 o;
            o.x = fmaf(xs, b.x, w.x);
            o.y = fmaf(xs, b.y, w.y);
            o.z = fmaf(xs, b.z, w.z);
            o.w = fmaf(xs, b.w, w.w);
            dst[c] = o;
        }

        // Rotate buffers (fully unrolled loop -> register renaming, no copies).
#pragma unroll
        for (int i = 0; i < 4; i++) cur[i] = nxt[i];
    }
}

extern "C" void kernel_launch(void* const* d_in, const int* in_sizes, int n_in,
                              void* d_out, int out_size)
{
    const float* input  = (const float*)d_in[0];
    const float* weight = (const float*)d_in[1];
    const float* bias   = (const float*)d_in[2];
    float* out = (float*)d_out;

    wsum_kernel<<<ODIM, 128>>>(weight, bias);
    fused_kernel<<<BDIM / RPB, 256>>>(input, bias, out);
}